// round 4
// baseline (speedup 1.0000x reference)
#include <cuda_runtime.h>

// ---------------------------------------------------------------------------
// SpectraLoRA fused: out = x@W^T + b + SCALING * sum_e g[b,e] * (x@A_e^T)@B_e^T
// Restructured:
//   gate[b,e]  = softmax(z@Wg^T + bg)
//   h'[m, e*16+r] = SCALING * gate[b,e] * (x[m] . A[e,r,:])     (GEMM K=768, N=128)
//   out[m,o]   = x[m].W[o,:] + bias[o] + h'[m,:] . BmT[o,:]     (GEMM K=768 then K=128)
// SIMT fp32 with packed fma.rn.f32x2 (sm_103a FFMA2).
// ---------------------------------------------------------------------------

#define IN_F   768
#define OUT_F  2304
#define NB     8
#define NS     2048
#define M_TOT  (NB*NS)      // 16384
#define NE     8
#define NR     16
#define ERDIM  (NE*NR)      // 128
#define GD     64
#define SCALING 2.0f        // ALPHA/R = 32/16

#define BM 128
#define BN 128
#define BK 16
#define TM 8
#define TN 8

typedef unsigned long long ull;

// scratch (no allocations allowed -> device globals)
__device__ float g_gate[NB * NE];              // 256 B
__device__ float g_BmT[OUT_F * ERDIM];         // 1.2 MB : BmT[o][e*16+r]
__device__ float g_h[(size_t)M_TOT * ERDIM];   // 8 MB   : gated, scaled down-proj

// ---- packed f32x2 helpers --------------------------------------------------
__device__ __forceinline__ ull pack2(float lo, float hi) {
    ull r;
    unsigned a = __float_as_uint(lo), b = __float_as_uint(hi);
    asm("mov.b64 %0, {%1,%2};" : "=l"(r) : "r"(a), "r"(b));
    return r;
}
__device__ __forceinline__ void unpack2(ull v, float& lo, float& hi) {
    unsigned a, b;
    asm("mov.b64 {%0,%1}, %2;" : "=r"(a), "=r"(b) : "l"(v));
    lo = __uint_as_float(a); hi = __uint_as_float(b);
}
__device__ __forceinline__ void ffma2(ull& c, ull a, ull b) {
    asm("fma.rn.f32x2 %0, %1, %2, %0;" : "+l"(c) : "l"(a), "l"(b));
}

// ---- tile load / store -----------------------------------------------------
// 256 threads load a 128x16 fp32 tile as float4s (coalesced on K), store
// transposed into smem S[k][row].
__device__ __forceinline__ void g_load(const float* __restrict__ src, int ld,
                                       int row0, int k0, int tid,
                                       float4& v0, float4& v1) {
    int r0 = tid >> 2, kq = tid & 3;
    v0 = *(const float4*)(src + (size_t)(row0 + r0)      * ld + k0 + kq * 4);
    v1 = *(const float4*)(src + (size_t)(row0 + r0 + 64) * ld + k0 + kq * 4);
}
__device__ __forceinline__ void s_store(float S[BK][BM], int tid,
                                        float4 v0, float4 v1) {
    int r0 = tid >> 2, kq = tid & 3;
    int kb = kq * 4;
    S[kb + 0][r0] = v0.x; S[kb + 1][r0] = v0.y;
    S[kb + 2][r0] = v0.z; S[kb + 3][r0] = v0.w;
    S[kb + 0][r0 + 64] = v1.x; S[kb + 1][r0 + 64] = v1.y;
    S[kb + 2][r0 + 64] = v1.z; S[kb + 3][r0 + 64] = v1.w;
}

// ---- 16-deep k-slab of 8x8 micro-tile, packed f32x2 FMAs -------------------
__device__ __forceinline__ void compute_tile(const float As[BK][BM],
                                             const float Bs[BK][BN],
                                             int tx, int ty, ull acc[TM][4]) {
#pragma unroll
    for (int kk = 0; kk < BK; kk++) {
        const float4 a0 = *(const float4*)&As[kk][ty * TM];
        const float4 a1 = *(const float4*)&As[kk][ty * TM + 4];
        const float4 b0 = *(const float4*)&Bs[kk][tx * TN];
        const float4 b1 = *(const float4*)&Bs[kk][tx * TN + 4];
        ull bp0 = pack2(b0.x, b0.y), bp1 = pack2(b0.z, b0.w);
        ull bp2 = pack2(b1.x, b1.y), bp3 = pack2(b1.z, b1.w);
        float av[TM] = {a0.x, a0.y, a0.z, a0.w, a1.x, a1.y, a1.z, a1.w};
#pragma unroll
        for (int mi = 0; mi < TM; mi++) {
            ull ad = pack2(av[mi], av[mi]);
            ffma2(acc[mi][0], ad, bp0);
            ffma2(acc[mi][1], ad, bp1);
            ffma2(acc[mi][2], ad, bp2);
            ffma2(acc[mi][3], ad, bp3);
        }
    }
}

// ---- one GEMM accumulation phase over kTiles*BK ----------------------------
__device__ __forceinline__ void gemm_phase(const float* __restrict__ Ap, int lda,
                                           const float* __restrict__ Bp, int ldb,
                                           int m0, int n0, int kTiles,
                                           float As[BK][BM], float Bs[BK][BN],
                                           ull acc[TM][4]) {
    const int tid = threadIdx.x;
    const int tx = tid & 15, ty = tid >> 4;
    float4 va0, va1, vb0, vb1;
    g_load(Ap, lda, m0, 0, tid, va0, va1);
    g_load(Bp, ldb, n0, 0, tid, vb0, vb1);
    s_store(As, tid, va0, va1);
    s_store(Bs, tid, vb0, vb1);
    __syncthreads();
    for (int t = 1; t < kTiles; t++) {
        g_load(Ap, lda, m0, t * BK, tid, va0, va1);
        g_load(Bp, ldb, n0, t * BK, tid, vb0, vb1);
        compute_tile(As, Bs, tx, ty, acc);
        __syncthreads();
        s_store(As, tid, va0, va1);
        s_store(Bs, tid, vb0, vb1);
        __syncthreads();
    }
    compute_tile(As, Bs, tx, ty, acc);
    __syncthreads();   // protect smem before next phase / reuse
}

// ---- kernel 1: gate = softmax(z@Wg^T + bg), [8,8] --------------------------
__global__ void gate_kernel(const float* __restrict__ z,
                            const float* __restrict__ Wg,
                            const float* __restrict__ bg) {
    __shared__ float sl[NB][NE];
    int tid = threadIdx.x;
    int b = tid >> 3, e = tid & 7;
    float s = bg[e];
#pragma unroll
    for (int g = 0; g < GD; g++) s += z[b * GD + g] * Wg[e * GD + g];
    sl[b][e] = s;
    __syncthreads();
    if (tid < NB) {
        int bb = tid;
        float mx = -1e30f;
        for (int k = 0; k < NE; k++) mx = fmaxf(mx, sl[bb][k]);
        float ex[NE]; float den = 0.f;
        for (int k = 0; k < NE; k++) { ex[k] = expf(sl[bb][k] - mx); den += ex[k]; }
        float inv = 1.f / den;
        for (int k = 0; k < NE; k++) g_gate[bb * NE + k] = ex[k] * inv;
    }
}

// ---- kernel 2: BmT[o][e*16+r] = Bm[e][o][r] --------------------------------
__global__ void bmt_kernel(const float* __restrict__ Bm) {
    int idx = blockIdx.x * blockDim.x + threadIdx.x;   // < OUT_F*ERDIM
    int o = idx >> 7, j = idx & 127;
    int e = j >> 4, r = j & 15;
    g_BmT[idx] = Bm[((size_t)e * OUT_F + o) * NR + r];
}

// ---- kernel 3: h' = SCALING * gate * (x @ A^T), [16384,128] ----------------
__global__ __launch_bounds__(256)
void h_kernel(const float* __restrict__ x, const float* __restrict__ A) {
    __shared__ float As[BK][BM];
    __shared__ float Bs[BK][BN];
    const int m0 = blockIdx.x * BM;
    ull acc[TM][4];
#pragma unroll
    for (int i = 0; i < TM; i++)
#pragma unroll
        for (int j = 0; j < 4; j++) acc[i][j] = 0ull;

    // A is [E,R,IN] contiguous == [128, 768] row-major: exactly the B-operand
    gemm_phase(x, IN_F, A, IN_F, m0, 0, IN_F / BK, As, Bs, acc);

    const int tx = threadIdx.x & 15, ty = threadIdx.x >> 4;
    const int b = m0 >> 11;                 // whole 128-row tile shares batch
#pragma unroll
    for (int mi = 0; mi < TM; mi++) {
        int m = m0 + ty * TM + mi;
        float* hrow = g_h + (size_t)m * ERDIM + tx * TN;
#pragma unroll
        for (int ni = 0; ni < 4; ni++) {
            int j = tx * TN + ni * 2;       // j even -> pair shares expert e
            float sc = SCALING * g_gate[b * NE + (j >> 4)];
            float lo, hi; unpack2(acc[mi][ni], lo, hi);
            float2 v; v.x = lo * sc; v.y = hi * sc;
            *(float2*)(hrow + ni * 2) = v;
        }
    }
}

// ---- kernel 4: out = x@W^T + bias + h'@BmT^T -------------------------------
__global__ __launch_bounds__(256)
void main_kernel(const float* __restrict__ x, const float* __restrict__ W,
                 const float* __restrict__ bias, float* __restrict__ out) {
    __shared__ float As[BK][BM];
    __shared__ float Bs[BK][BN];
    const int n0 = blockIdx.x * BN;
    const int m0 = blockIdx.y * BM;
    ull acc[TM][4];
#pragma unroll
    for (int i = 0; i < TM; i++)
#pragma unroll
        for (int j = 0; j < 4; j++) acc[i][j] = 0ull;

    gemm_phase(x,   IN_F,  W,      IN_F,  m0, n0, IN_F / BK,  As, Bs, acc);
    gemm_phase(g_h, ERDIM, g_BmT,  ERDIM, m0, n0, ERDIM / BK, As, Bs, acc);

    const int tx = threadIdx.x & 15, ty = threadIdx.x >> 4;
#pragma unroll
    for (int mi = 0; mi < TM; mi++) {
        int m = m0 + ty * TM + mi;
        float* orow = out + (size_t)m * OUT_F + n0 + tx * TN;
#pragma unroll
        for (int ni = 0; ni < 4; ni++) {
            int j = n0 + tx * TN + ni * 2;
            float lo, hi; unpack2(acc[mi][ni], lo, hi);
            float2 v; v.x = lo + bias[j]; v.y = hi + bias[j + 1];
            *(float2*)(orow + ni * 2) = v;
        }
    }
}

// ---------------------------------------------------------------------------
extern "C" void kernel_launch(void* const* d_in, const int* in_sizes, int n_in,
                              void* d_out, int out_size) {
    const float* x  = (const float*)d_in[0];   // [8,2048,768]
    const float* z  = (const float*)d_in[1];   // [8,64]
    const float* W  = (const float*)d_in[2];   // [2304,768]
    const float* b  = (const float*)d_in[3];   // [2304]
    const float* A  = (const float*)d_in[4];   // [8,16,768]
    const float* Bm = (const float*)d_in[5];   // [8,2304,16]
    const float* Wg = (const float*)d_in[6];   // [8,64]
    const float* bg = (const float*)d_in[7];   // [8]
    float* out = (float*)d_out;                // [8,2048,2304]

    gate_kernel<<<1, 64>>>(z, Wg, bg);
    bmt_kernel<<<(OUT_F * ERDIM) / 1024, 1024>>>(Bm);
    h_kernel<<<M_TOT / BM, 256>>>(x, A);
    main_kernel<<<dim3(OUT_F / BN, M_TOT / BM), 256>>>(x, W, b, out);
}

// round 8
// speedup vs baseline: 5.4314x; 5.4314x over previous
#include <cuda_runtime.h>
#include <cstdint>

// ---------------------------------------------------------------------------
// SpectraLoRA fused, mma.sync tf32 edition (tcgen05 rejected by toolchain:
// .target sm_103 without 'a' features).
//   gate[b,e]     = softmax(z@Wg^T + bg)                        (tiny SIMT)
//   BmT[o][e16+r] = Bm[e][o][r]                                 (transpose)
//   g_h[m][j]     = SCALING*gate[b,j>>4] * (x[m] . A[j])        (tf32 mma)
//   out[m][o]     = x[m].W[o] + bias[o] + g_h[m].BmT[o]         (tf32 mma,
//                    K=768 frozen + K=128 LoRA share one accumulator tile)
// Smem: row-major [row][k], stride 36 words -> STS.128 at the 4-phase floor,
// LDS fragment reads conflict-free (bank = 4g + t + const).
// ---------------------------------------------------------------------------

#define IN_F   768
#define OUT_F  2304
#define NBATCH 8
#define M_TOT  16384
#define NE     8
#define NR     16
#define ERDIM  128
#define GD     64
#define SCALING 2.0f

#define BM 128
#define BN 128
#define BK 32
#define SPAD 36         // words per smem row (32 data + 4 pad)

__device__ float g_gate[NBATCH * NE];
__device__ float g_BmT[OUT_F * ERDIM];
__device__ float g_h[(size_t)M_TOT * ERDIM];

// ---- tf32 helpers ----------------------------------------------------------
static __device__ __forceinline__ uint32_t f2tf32(float f) {
    uint32_t u;
    asm("cvt.rna.tf32.f32 %0, %1;" : "=r"(u) : "f"(f));
    return u;
}
static __device__ __forceinline__ void mma_tf32(float d[4], const uint32_t a[4],
                                                const uint32_t b[2]) {
    asm volatile(
        "mma.sync.aligned.m16n8k8.row.col.f32.tf32.tf32.f32 "
        "{%0,%1,%2,%3}, {%4,%5,%6,%7}, {%8,%9}, {%0,%1,%2,%3};"
        : "+f"(d[0]), "+f"(d[1]), "+f"(d[2]), "+f"(d[3])
        : "r"(a[0]), "r"(a[1]), "r"(a[2]), "r"(a[3]), "r"(b[0]), "r"(b[1]));
}

// ---- tile load / store -----------------------------------------------------
// 256 threads: kq = tid&7 (k quad), r0 = tid>>3 (0..31). Each thread loads
// rows r0+32*i (i=0..3), k = k0 + kq*4 .. +3  -> full 128x32 tile.
static __device__ __forceinline__ void g_load(const float* __restrict__ src,
                                              int ld, int row0, int k0, int tid,
                                              float4 v[4]) {
    const int kq = tid & 7, r0 = tid >> 3;
#pragma unroll
    for (int i = 0; i < 4; i++)
        v[i] = *(const float4*)(src + (size_t)(row0 + r0 + 32 * i) * ld + k0 + kq * 4);
}
static __device__ __forceinline__ void s_store(uint32_t S[][SPAD], int tid,
                                               const float4 v[4]) {
    const int kq = tid & 7, r0 = tid >> 3;
#pragma unroll
    for (int i = 0; i < 4; i++) {
        uint4 u;
        u.x = f2tf32(v[i].x); u.y = f2tf32(v[i].y);
        u.z = f2tf32(v[i].z); u.w = f2tf32(v[i].w);
        *(uint4*)&S[r0 + 32 * i][kq * 4] = u;
    }
}

// ---- warp MMA over one BK=32 slab -----------------------------------------
// Warp tile 64x32: wm in {0,1}, wn in {0..3}. acc[mi][ni][4].
static __device__ __forceinline__ void compute_tile(const uint32_t As[BM][SPAD],
                                                    const uint32_t Bs[BN][SPAD],
                                                    int wm, int wn, int g, int t,
                                                    float acc[4][4][4]) {
#pragma unroll
    for (int kk = 0; kk < 4; kk++) {
        const int k8 = kk * 8;
        uint32_t af[4][4], bf[4][2];
#pragma unroll
        for (int mi = 0; mi < 4; mi++) {
            const int m = wm * 64 + mi * 16 + g;
            af[mi][0] = As[m][k8 + t];
            af[mi][1] = As[m + 8][k8 + t];
            af[mi][2] = As[m][k8 + t + 4];
            af[mi][3] = As[m + 8][k8 + t + 4];
        }
#pragma unroll
        for (int ni = 0; ni < 4; ni++) {
            const int n = wn * 32 + ni * 8 + g;
            bf[ni][0] = Bs[n][k8 + t];
            bf[ni][1] = Bs[n][k8 + t + 4];
        }
#pragma unroll
        for (int mi = 0; mi < 4; mi++)
#pragma unroll
            for (int ni = 0; ni < 4; ni++)
                mma_tf32(acc[mi][ni], af[mi], bf[ni]);
    }
}

// ---- kernel 1: gate = softmax(z@Wg^T + bg) ---------------------------------
__global__ void gate_kernel(const float* __restrict__ z,
                            const float* __restrict__ Wg,
                            const float* __restrict__ bg) {
    __shared__ float sl[NBATCH][NE];
    int tid = threadIdx.x;
    int b = tid >> 3, e = tid & 7;
    float s = bg[e];
#pragma unroll
    for (int g = 0; g < GD; g++) s += z[b * GD + g] * Wg[e * GD + g];
    sl[b][e] = s;
    __syncthreads();
    if (tid < NBATCH) {
        int bb = tid;
        float mx = -1e30f;
        for (int k = 0; k < NE; k++) mx = fmaxf(mx, sl[bb][k]);
        float ex[NE]; float den = 0.f;
        for (int k = 0; k < NE; k++) { ex[k] = expf(sl[bb][k] - mx); den += ex[k]; }
        float inv = 1.f / den;
        for (int k = 0; k < NE; k++) g_gate[bb * NE + k] = ex[k] * inv;
    }
}

// ---- kernel 2: BmT[o][e*16+r] = Bm[e][o][r] --------------------------------
__global__ void bmt_kernel(const float* __restrict__ Bm) {
    int idx = blockIdx.x * blockDim.x + threadIdx.x;
    int o = idx >> 7, j = idx & 127;
    int e = j >> 4, r = j & 15;
    g_BmT[idx] = Bm[((size_t)e * OUT_F + o) * NR + r];
}

// ---- kernel 3: g_h = SCALING * gate ⊙ (x @ A^T) ----------------------------
__global__ __launch_bounds__(256)
void h_mma_kernel(const float* __restrict__ x, const float* __restrict__ Al) {
    __shared__ uint32_t As[BM][SPAD];
    __shared__ uint32_t Bs[BN][SPAD];
    const int tid = threadIdx.x, warp = tid >> 5, lane = tid & 31;
    const int wm = warp >> 2, wn = warp & 3;
    const int g = lane >> 2, t = lane & 3;
    const int m0 = blockIdx.x * BM;

    float acc[4][4][4];
#pragma unroll
    for (int i = 0; i < 4; i++)
#pragma unroll
        for (int j = 0; j < 4; j++)
#pragma unroll
            for (int r = 0; r < 4; r++) acc[i][j][r] = 0.f;

    float4 va[4], vb[4];
    g_load(x, IN_F, m0, 0, tid, va);
    g_load(Al, IN_F, 0, 0, tid, vb);
    s_store(As, tid, va);
    s_store(Bs, tid, vb);
    __syncthreads();
    for (int tt = 1; tt < IN_F / BK; tt++) {
        g_load(x, IN_F, m0, tt * BK, tid, va);
        g_load(Al, IN_F, 0, tt * BK, tid, vb);
        compute_tile(As, Bs, wm, wn, g, t, acc);
        __syncthreads();
        s_store(As, tid, va);
        s_store(Bs, tid, vb);
        __syncthreads();
    }
    compute_tile(As, Bs, wm, wn, g, t, acc);

    // epilogue: scale by SCALING * gate[batch, col>>4]
    const int bt = m0 >> 11;            // 128-row tile lies in one batch
#pragma unroll
    for (int mi = 0; mi < 4; mi++) {
        const int row = m0 + wm * 64 + mi * 16 + g;
#pragma unroll
        for (int ni = 0; ni < 4; ni++) {
            const int col = wn * 32 + ni * 8 + 2 * t;   // even; pair same expert
            const float s = SCALING * g_gate[bt * NE + (col >> 4)];
            float2 v0 = make_float2(acc[mi][ni][0] * s, acc[mi][ni][1] * s);
            float2 v1 = make_float2(acc[mi][ni][2] * s, acc[mi][ni][3] * s);
            *(float2*)(g_h + (size_t)row * ERDIM + col) = v0;
            *(float2*)(g_h + (size_t)(row + 8) * ERDIM + col) = v1;
        }
    }
}

// ---- kernel 4: out = x@W^T + bias + g_h@BmT^T ------------------------------
__global__ __launch_bounds__(256)
void main_mma_kernel(const float* __restrict__ x, const float* __restrict__ W,
                     const float* __restrict__ bias, float* __restrict__ out) {
    __shared__ uint32_t As[BM][SPAD];
    __shared__ uint32_t Bs[BN][SPAD];
    const int tid = threadIdx.x, warp = tid >> 5, lane = tid & 31;
    const int wm = warp >> 2, wn = warp & 3;
    const int g = lane >> 2, t = lane & 3;
    const int m0 = blockIdx.y * BM, n0 = blockIdx.x * BN;

    float acc[4][4][4];
#pragma unroll
    for (int i = 0; i < 4; i++)
#pragma unroll
        for (int j = 0; j < 4; j++)
#pragma unroll
            for (int r = 0; r < 4; r++) acc[i][j][r] = 0.f;

    const int T1 = IN_F / BK;           // 24 frozen tiles
    const int T2 = ERDIM / BK;          // 4 LoRA tiles
    float4 va[4], vb[4];
    g_load(x, IN_F, m0, 0, tid, va);
    g_load(W, IN_F, n0, 0, tid, vb);
    s_store(As, tid, va);
    s_store(Bs, tid, vb);
    __syncthreads();
    for (int tt = 1; tt < T1 + T2; tt++) {
        if (tt < T1) {
            g_load(x, IN_F, m0, tt * BK, tid, va);
            g_load(W, IN_F, n0, tt * BK, tid, vb);
        } else {
            g_load(g_h, ERDIM, m0, (tt - T1) * BK, tid, va);
            g_load(g_BmT, ERDIM, n0, (tt - T1) * BK, tid, vb);
        }
        compute_tile(As, Bs, wm, wn, g, t, acc);
        __syncthreads();
        s_store(As, tid, va);
        s_store(Bs, tid, vb);
        __syncthreads();
    }
    compute_tile(As, Bs, wm, wn, g, t, acc);

    // epilogue: + bias, store
#pragma unroll
    for (int mi = 0; mi < 4; mi++) {
        const int row = m0 + wm * 64 + mi * 16 + g;
#pragma unroll
        for (int ni = 0; ni < 4; ni++) {
            const int col = n0 + wn * 32 + ni * 8 + 2 * t;
            const float2 bb = *(const float2*)(bias + col);
            float2 v0 = make_float2(acc[mi][ni][0] + bb.x, acc[mi][ni][1] + bb.y);
            float2 v1 = make_float2(acc[mi][ni][2] + bb.x, acc[mi][ni][3] + bb.y);
            *(float2*)(out + (size_t)row * OUT_F + col) = v0;
            *(float2*)(out + (size_t)(row + 8) * OUT_F + col) = v1;
        }
    }
}

// ---------------------------------------------------------------------------
extern "C" void kernel_launch(void* const* d_in, const int* in_sizes, int n_in,
                              void* d_out, int out_size) {
    const float* x  = (const float*)d_in[0];   // [8,2048,768]
    const float* z  = (const float*)d_in[1];   // [8,64]
    const float* W  = (const float*)d_in[2];   // [2304,768]
    const float* b  = (const float*)d_in[3];   // [2304]
    const float* A  = (const float*)d_in[4];   // [8,16,768]
    const float* Bm = (const float*)d_in[5];   // [8,2304,16]
    const float* Wg = (const float*)d_in[6];   // [8,64]
    const float* bg = (const float*)d_in[7];   // [8]
    float* out = (float*)d_out;                // [8,2048,2304]

    gate_kernel<<<1, 64>>>(z, Wg, bg);
    bmt_kernel<<<(OUT_F * ERDIM) / 1024, 1024>>>(Bm);
    h_mma_kernel<<<M_TOT / BM, 256>>>(x, A);
    main_mma_kernel<<<dim3(OUT_F / BN, M_TOT / BM), 256>>>(x, W, b, out);
}